// round 13
// baseline (speedup 1.0000x reference)
#include <cuda_runtime.h>
#include <math_constants.h>

// Batched nearest-neighbor argmin + gather — FINAL (at chip streaming ceiling).
//   y: [B,2] f32, Y_surf: [B,2,G] f32, U_grid: [2,G] f32, out: [B,2] f32
//   out[b,:] = U_grid[:, argmin_g ||Y_surf[b,:,g] - y[b,:]||^2]
//
// Converged config (12 rounds): 50.1us ncu, 83.6% DRAM, 6623 GB/s =
// ~99% of the measured path-independent LTS/HBM floor (LDG == ldcs == TMA)
// for the compulsory 327.7 MB single-pass read.
//  - Block-per-sample, 128 thr: HW overlaps dying CTA epilogues with fresh
//    CTA loads (beats persistent/pipelined variants, measured 3x).
//  - Plain LDG float4, x2 unroll (MLP_p1=4 sweet spot; x4 regresses via
//    L1tex-queue contention; __ldcs ~-3% DRAM).
//  - 4 independent argmin accumulators: depth-1 predicated update chains.
//  - Packed u64 (d2bits<<32 | idx) min reduction; d2 >= 0 so IEEE bits are
//    order-monotone as u32 -> exact jnp.argmin first-index tie-break.
//  - LDG.64 y read, STG.64 epilogue store.

#define NT 128

struct Acc { float d[4]; int g[4]; };

__device__ __forceinline__ void proc4(const float4& a, const float4& c, int g,
                                      float y0, float y1, Acc& acc) {
    float dx, dz, d;
    dx = a.x - y0; dz = c.x - y1; d = dx * dx + dz * dz;
    if (d < acc.d[0]) { acc.d[0] = d; acc.g[0] = g + 0; }
    dx = a.y - y0; dz = c.y - y1; d = dx * dx + dz * dz;
    if (d < acc.d[1]) { acc.d[1] = d; acc.g[1] = g + 1; }
    dx = a.z - y0; dz = c.z - y1; d = dx * dx + dz * dz;
    if (d < acc.d[2]) { acc.d[2] = d; acc.g[2] = g + 2; }
    dx = a.w - y0; dz = c.w - y1; d = dx * dx + dz * dz;
    if (d < acc.d[3]) { acc.d[3] = d; acc.g[3] = g + 3; }
}

__device__ __forceinline__ unsigned long long pack(float d, int g) {
    return ((unsigned long long)__float_as_uint(d) << 32) | (unsigned)g;
}

__global__ __launch_bounds__(NT)
void lqr_argmin_kernel(const float* __restrict__ y,
                       const float* __restrict__ Ys,
                       const float* __restrict__ Ug,
                       float* __restrict__ out,
                       int G) {
    const int b   = blockIdx.x;
    const int tid = threadIdx.x;

    const float2 yb = __ldg(reinterpret_cast<const float2*>(y) + b);
    const float y0 = yb.x;
    const float y1 = yb.y;

    const float4* __restrict__ v0 =
        reinterpret_cast<const float4*>(Ys + (size_t)b * 2 * G);
    const float4* __restrict__ v1 = v0 + (G >> 2);
    const int n4 = G >> 2;  // G % 4 == 0 (G = 2500)

    Acc acc;
    #pragma unroll
    for (int k = 0; k < 4; k++) { acc.d[k] = CUDART_INF_F; acc.g[k] = 0; }

    int i = tid;
    // x2 unroll: 4 independent 128-bit loads in flight per thread.
    for (; i + NT < n4; i += 2 * NT) {
        float4 a0 = v0[i];
        float4 a1 = v0[i + NT];
        float4 c0 = v1[i];
        float4 c1 = v1[i + NT];
        proc4(a0, c0, i << 2,        y0, y1, acc);
        proc4(a1, c1, (i + NT) << 2, y0, y1, acc);
    }
    if (i < n4) {
        float4 a = v0[i];
        float4 c = v1[i];
        proc4(a, c, i << 2, y0, y1, acc);
    }

    // Packed u64 min == (min d2, tie -> min idx) lexicographic.
    unsigned long long best = pack(acc.d[0], acc.g[0]);
    #pragma unroll
    for (int k = 1; k < 4; k++) {
        unsigned long long o = pack(acc.d[k], acc.g[k]);
        if (o < best) best = o;
    }

    #pragma unroll
    for (int off = 16; off > 0; off >>= 1) {
        unsigned long long o = __shfl_down_sync(0xffffffffu, best, off);
        if (o < best) best = o;
    }

    __shared__ unsigned long long sb[NT / 32];
    const int w = tid >> 5;
    if ((tid & 31) == 0) sb[w] = best;
    __syncthreads();

    if (w == 0) {
        const int nw = NT / 32;
        best = (tid < nw) ? sb[tid] : 0xffffffffffffffffULL;
        #pragma unroll
        for (int off = 16; off > 0; off >>= 1) {
            unsigned long long o = __shfl_down_sync(0xffffffffu, best, off);
            if (o < best) best = o;
        }
        if (tid == 0) {
            const int bidx = (int)(unsigned)best;
            float2 u;
            u.x = __ldg(&Ug[bidx]);
            u.y = __ldg(&Ug[(size_t)G + bidx]);
            reinterpret_cast<float2*>(out)[b] = u;  // one STG.64
        }
    }
}

extern "C" void kernel_launch(void* const* d_in, const int* in_sizes, int n_in,
                              void* d_out, int out_size) {
    const float* y  = (const float*)d_in[0];   // [B, 2]
    const float* Ys = (const float*)d_in[1];   // [B, 2, G]
    const float* Ug = (const float*)d_in[2];   // [2, G]
    float* out = (float*)d_out;                // [B, 2]

    const int B = in_sizes[0] / 2;
    const int G = in_sizes[2] / 2;

    lqr_argmin_kernel<<<B, NT>>>(y, Ys, Ug, out, G);
}